// round 13
// baseline (speedup 1.0000x reference)
#include <cuda_runtime.h>
#include <cuda_fp16.h>
#include <cstdint>
#include <cstddef>

// ============================================================================
// NaiveFourierKANLayer on GB300 (sm_103a harness targets compute_103 ->
// tcgen05 unavailable; mma.sync HMMA path).
// GEMM: Y[8192,1024] = F[8192,16384] @ Wh[1024,16384]^T  (fp16 in, fp32 acc)
//   kidx = t*8192 + i*8 + k   (t=0 cos, t=1 sin; harmonic k+1)
// R13: ks0 LDSM batch peeled to directly after the barrier, ahead of the
//      cp.async produce block, so LDS latency overlaps produce-issue instead
//      of stalling the first MMA. Everything else identical to R12
//      (128x128 CTA, 64x32 warps, 2 CTAs/SM, 3-stage cp.async, split-K=4,
//      ks stagger, REDG epilogue, contiguous-store prep).
// ============================================================================

#define DI __device__ __forceinline__

static constexpr int BATCH  = 8192;
static constexpr int INDIM  = 1024;
static constexpr int OUTDIM = 1024;
static constexpr int GRID   = 8;
static constexpr int KTOT   = INDIM * 2 * GRID;   // 16384

__device__ __half F_scratch[(size_t)BATCH * KTOT];    // 268 MB
__device__ __half W_scratch[(size_t)OUTDIM * KTOT];   // 32 MB

// ----------------------------------------------------------------------------
// Pass 1 (merged): features (2 elems/thread), W convert, output zero-fill.
// All scratch stores are uint4 with warp-contiguous addressing.
// ----------------------------------------------------------------------------
static constexpr int FEAT_BLOCKS  = (BATCH * INDIM) / 512;          // 16384
static constexpr int WCONV_BLOCKS = (2 * OUTDIM * INDIM) / 256;     // 8192
static constexpr int ZERO_BLOCKS  = (BATCH * OUTDIM / 4) / 256;     // 8192
static constexpr int PREP_BLOCKS  = FEAT_BLOCKS + WCONV_BLOCKS + ZERO_BLOCKS;

__global__ void prep_kernel(const float* __restrict__ x,
                            const float* __restrict__ fc,
                            float4* __restrict__ out4) {
    int blk = blockIdx.x;
    if (blk < FEAT_BLOCKS) {
        uint4* F4 = reinterpret_cast<uint4*>(F_scratch);
        int base = blk * 512 + threadIdx.x;      // element id = b*1024 + i
        float xv0 = x[base];
        float xv1 = x[base + 256];

        float s0, c0, s1, c1;
        __sincosf(xv0, &s0, &c0);
        __sincosf(xv1, &s1, &c1);

        union { __half h[8]; uint4 v; } uc0, us0, uc1, us1;
        float ck0 = c0, sk0 = s0, ck1 = c1, sk1 = s1;
        uc0.h[0] = __float2half_rn(c0);  us0.h[0] = __float2half_rn(s0);
        uc1.h[0] = __float2half_rn(c1);  us1.h[0] = __float2half_rn(s1);
#pragma unroll
        for (int k = 1; k < GRID; k++) {
            float cn0 = ck0 * c0 - sk0 * s0;
            float sn0 = sk0 * c0 + ck0 * s0;
            float cn1 = ck1 * c1 - sk1 * s1;
            float sn1 = sk1 * c1 + ck1 * s1;
            ck0 = cn0; sk0 = sn0; ck1 = cn1; sk1 = sn1;
            uc0.h[k] = __float2half_rn(ck0);  us0.h[k] = __float2half_rn(sk0);
            uc1.h[k] = __float2half_rn(ck1);  us1.h[k] = __float2half_rn(sk1);
        }
        int b0 = base >> 10,         i0 = base & 1023;
        int b1 = (base + 256) >> 10, i1 = (base + 256) & 1023;
        F4[(size_t)b0 * 2048 + i0]        = uc0.v;
        F4[(size_t)b0 * 2048 + 1024 + i0] = us0.v;
        F4[(size_t)b1 * 2048 + i1]        = uc1.v;
        F4[(size_t)b1 * 2048 + 1024 + i1] = us1.v;
    } else if (blk < FEAT_BLOCKS + WCONV_BLOCKS) {
        uint4* W4 = reinterpret_cast<uint4*>(W_scratch);
        int gid = (blk - FEAT_BLOCKS) * blockDim.x + threadIdx.x; // (t*1024+j)*1024+i
        int i = gid & 1023;
        int j = (gid >> 10) & 1023;
        int t = gid >> 20;

        const float4* src = reinterpret_cast<const float4*>(fc + (size_t)gid * 8);
        float4 a = src[0], b = src[1];

        union { __half h[8]; uint4 v; } u;
        u.h[0] = __float2half_rn(a.x); u.h[1] = __float2half_rn(a.y);
        u.h[2] = __float2half_rn(a.z); u.h[3] = __float2half_rn(a.w);
        u.h[4] = __float2half_rn(b.x); u.h[5] = __float2half_rn(b.y);
        u.h[6] = __float2half_rn(b.z); u.h[7] = __float2half_rn(b.w);

        W4[(size_t)j * 2048 + t * 1024 + i] = u.v;
    } else {
        int gid = (blk - FEAT_BLOCKS - WCONV_BLOCKS) * blockDim.x + threadIdx.x;
        out4[gid] = make_float4(0.f, 0.f, 0.f, 0.f);
    }
}

// ----------------------------------------------------------------------------
// Pass 2: mma.sync GEMM.  CTA 128x128xKT=64, 8 warps (2x4), warp 64x32.
// Split-K = 4: each CTA handles 64 of 256 K-iterations, REDG epilogue.
// ----------------------------------------------------------------------------
static constexpr int MT = 128;
static constexpr int NT = 128;
static constexpr int KT = 64;                 // 64 halves = 128 B per row
static constexpr int STAGES = 3;
static constexpr int SPLITK = 4;
static constexpr int ITERS_PER_CTA = KTOT / KT / SPLITK;   // 64

static constexpr int TILE_BYTES = MT * 128;              // 16384 per operand
static constexpr int STAGE_BYTES = 2 * TILE_BYTES;       // A + B = 32768
static constexpr int SMEM_BYTES = STAGES * STAGE_BYTES;  // 98304 per CTA

DI uint32_t swz(uint32_t off) { return off ^ ((off >> 3) & 0x70); }

DI void cp_async16(uint32_t dst, const void* src) {
    asm volatile("cp.async.cg.shared.global [%0], [%1], 16;"
                 :: "r"(dst), "l"(src) : "memory");
}
DI void cp_commit() { asm volatile("cp.async.commit_group;" ::: "memory"); }

DI void ldmatrix_x4(uint32_t* r, uint32_t addr) {
    asm volatile("ldmatrix.sync.aligned.m8n8.x4.shared.b16 {%0,%1,%2,%3}, [%4];"
                 : "=r"(r[0]), "=r"(r[1]), "=r"(r[2]), "=r"(r[3]) : "r"(addr));
}

DI void mma16816(float* c, const uint32_t* a, const uint32_t* b) {
    asm volatile(
        "mma.sync.aligned.m16n8k16.row.col.f32.f16.f16.f32 "
        "{%0,%1,%2,%3}, {%4,%5,%6,%7}, {%8,%9}, {%0,%1,%2,%3};"
        : "+f"(c[0]), "+f"(c[1]), "+f"(c[2]), "+f"(c[3])
        : "r"(a[0]), "r"(a[1]), "r"(a[2]), "r"(a[3]), "r"(b[0]), "r"(b[1]));
}

DI void red_add(float* addr, float v) {
    asm volatile("red.global.add.f32 [%0], %1;" :: "l"(addr), "f"(v) : "memory");
}

extern __shared__ char gemm_smem[];

DI void load_stage(int stage, int tid, uint32_t smem_u32,
                   int m0, int n0, int kiter_base) {
    int slot = stage % STAGES;
    uint32_t a_base = smem_u32 + slot * STAGE_BYTES;
    uint32_t b_base = a_base + TILE_BYTES;
    size_t koff = (size_t)(kiter_base + stage) * KT;
    const __half* Fp = F_scratch + (size_t)m0 * KTOT + koff;
    const __half* Wp = W_scratch + (size_t)n0 * KTOT + koff;

#pragma unroll
    for (int it = 0; it < 4; it++) {
        int c = tid + it * 256;
        int row = c >> 3, col = c & 7;
        cp_async16(a_base + swz((uint32_t)row * 128 + (uint32_t)col * 16),
                   Fp + (size_t)row * KTOT + col * 8);
    }
#pragma unroll
    for (int it = 0; it < 4; it++) {
        int c = tid + it * 256;
        int row = c >> 3, col = c & 7;
        cp_async16(b_base + swz((uint32_t)row * 128 + (uint32_t)col * 16),
                   Wp + (size_t)row * KTOT + col * 8);
    }
    cp_commit();
}

// LDSM batch for one k-sub-step into fragment arrays.
DI void ldsm_batch(uint32_t af[4][4], uint32_t bf[4][2],
                   uint32_t a_base, uint32_t b_base,
                   uint32_t a_lane_off, uint32_t b_lane_off, uint32_t kb) {
#pragma unroll
    for (int mi = 0; mi < 4; mi++)
        ldmatrix_x4(af[mi], a_base +
                    swz(a_lane_off + (uint32_t)(mi * 16) * 128 + kb));
#pragma unroll
    for (int g = 0; g < 2; g++) {
        uint32_t r[4];
        ldmatrix_x4(r, b_base +
                    swz(b_lane_off + (uint32_t)(g * 16) * 128 + kb));
        bf[g * 2 + 0][0] = r[0]; bf[g * 2 + 0][1] = r[1];
        bf[g * 2 + 1][0] = r[2]; bf[g * 2 + 1][1] = r[3];
    }
}

__global__ void __launch_bounds__(256, 2)
gemm_kernel(float* __restrict__ out) {
    uint32_t smem_u32 = (uint32_t)__cvta_generic_to_shared(gemm_smem);
    int tid = threadIdx.x;
    int wid = tid >> 5, lid = tid & 31;
    int wm = wid >> 2;          // 0..1 : warp M tile of 64
    int wn = wid & 3;           // 0..3 : warp N tile of 32
    int n0 = blockIdx.x * NT;
    int m0 = blockIdx.y * MT;
    int kiter_base = blockIdx.z * ITERS_PER_CTA;

    float acc[4][4][4];
#pragma unroll
    for (int mi = 0; mi < 4; mi++)
#pragma unroll
        for (int ni = 0; ni < 4; ni++)
#pragma unroll
            for (int q = 0; q < 4; q++) acc[mi][ni][q] = 0.0f;

    // ldmatrix lane address components (pre-swizzle, within tile)
    int a_row_lane = lid & 15;
    int a_koff_lane = (lid >> 4) << 4;               // 0 or 16 bytes
    int b_row_lane = (lid & 7) + ((lid >> 4) << 3);
    int b_koff_lane = ((lid >> 3) & 1) << 4;

    uint32_t a_lane_off = (uint32_t)(wm * 64 + a_row_lane) * 128 + a_koff_lane;
    uint32_t b_lane_off = (uint32_t)(wn * 32 + b_row_lane) * 128 + b_koff_lane;

    // Prologue: fill 2 of 3 stages.
    load_stage(0, tid, smem_u32, m0, n0, kiter_base);
    load_stage(1, tid, smem_u32, m0, n0, kiter_base);

    for (int s = 0; s < ITERS_PER_CTA; s++) {
        int slot = s % STAGES;

        if (s + 1 < ITERS_PER_CTA)
            asm volatile("cp.async.wait_group 1;" ::: "memory");
        else
            asm volatile("cp.async.wait_group 0;" ::: "memory");
        __syncthreads();   // all threads' stage-s data visible; slot of s-1 free

        uint32_t a_base = smem_u32 + slot * STAGE_BYTES;
        uint32_t b_base = a_base + TILE_BYTES;

        // Peel: issue the first k-sub-step's LDSM immediately after the
        // barrier, so its latency overlaps the produce-issue below.
        uint32_t af[4][4];
        uint32_t bf[4][2];
        ldsm_batch(af, bf, a_base, b_base, a_lane_off, b_lane_off,
                   (uint32_t)((wid & 3) * 32));

        if (s + 2 < ITERS_PER_CTA)
            load_stage(s + 2, tid, smem_u32, m0, n0, kiter_base);

        // Per-warp phase stagger over the 4 k-sub-steps.
#pragma unroll
        for (int ks = 0; ks < 4; ks++) {
#pragma unroll
            for (int mi = 0; mi < 4; mi++)
#pragma unroll
                for (int ni = 0; ni < 4; ni++)
                    mma16816(acc[mi][ni], af[mi], bf[ni]);
            if (ks < 3)
                ldsm_batch(af, bf, a_base, b_base, a_lane_off, b_lane_off,
                           (uint32_t)(((ks + 1 + wid) & 3) * 32));
        }
    }

    // Epilogue: accumulate partial tile into gmem via L2 reductions.
    int qr = lid >> 2;
    int qc = lid & 3;
#pragma unroll
    for (int mi = 0; mi < 4; mi++) {
        int row_a = m0 + wm * 64 + mi * 16 + qr;
        int row_b = row_a + 8;
#pragma unroll
        for (int ni = 0; ni < 4; ni++) {
            int col = n0 + wn * 32 + ni * 8 + qc * 2;
            float* pa = out + (size_t)row_a * OUTDIM + col;
            float* pb = out + (size_t)row_b * OUTDIM + col;
            red_add(pa + 0, acc[mi][ni][0]);
            red_add(pa + 1, acc[mi][ni][1]);
            red_add(pb + 0, acc[mi][ni][2]);
            red_add(pb + 1, acc[mi][ni][3]);
        }
    }
}

// ----------------------------------------------------------------------------
// kernel_launch
// ----------------------------------------------------------------------------
extern "C" void kernel_launch(void* const* d_in, const int* in_sizes, int n_in,
                              void* d_out, int out_size) {
    const float* x  = (const float*)d_in[0];    // [8192, 1024]
    const float* fc = (const float*)d_in[1];    // [2, 1024, 1024, 8]
    float* out = (float*)d_out;                 // [8192, 1024]

    prep_kernel<<<PREP_BLOCKS, 256>>>(x, fc, (float4*)out);

    cudaFuncSetAttribute(gemm_kernel,
                         cudaFuncAttributeMaxDynamicSharedMemorySize, SMEM_BYTES);
    gemm_kernel<<<dim3(OUTDIM / NT, BATCH / MT, SPLITK), 256, SMEM_BYTES>>>(out);
}

// round 14
// speedup vs baseline: 1.0375x; 1.0375x over previous
#include <cuda_runtime.h>
#include <cuda_fp16.h>
#include <cstdint>
#include <cstddef>

// ============================================================================
// NaiveFourierKANLayer on GB300 (sm_103a harness targets compute_103 ->
// tcgen05 unavailable; mma.sync HMMA path).
// GEMM: Y[8192,1024] = F[8192,16384] @ Wh[1024,16384]^T  (fp16 in, fp32 acc)
//   kidx = t*8192 + i*8 + k   (t=0 cos, t=1 sin; harmonic k+1)
// R14: R12 mainloop restored verbatim (R13 peel regressed: +alu, -tensor).
//      Epilogue switched to red.global.add.v2.f32 (half the atomic instr).
//      Core: 128x128 CTA, 64x32 warps, 2 CTAs/SM, 3-stage cp.async,
//      split-K=4, ks stagger, contiguous-store prep.
// ============================================================================

#define DI __device__ __forceinline__

static constexpr int BATCH  = 8192;
static constexpr int INDIM  = 1024;
static constexpr int OUTDIM = 1024;
static constexpr int GRID   = 8;
static constexpr int KTOT   = INDIM * 2 * GRID;   // 16384

__device__ __half F_scratch[(size_t)BATCH * KTOT];    // 268 MB
__device__ __half W_scratch[(size_t)OUTDIM * KTOT];   // 32 MB

// ----------------------------------------------------------------------------
// Pass 1 (merged): features (2 elems/thread), W convert, output zero-fill.
// All scratch stores are uint4 with warp-contiguous addressing.
// ----------------------------------------------------------------------------
static constexpr int FEAT_BLOCKS  = (BATCH * INDIM) / 512;          // 16384
static constexpr int WCONV_BLOCKS = (2 * OUTDIM * INDIM) / 256;     // 8192
static constexpr int ZERO_BLOCKS  = (BATCH * OUTDIM / 4) / 256;     // 8192
static constexpr int PREP_BLOCKS  = FEAT_BLOCKS + WCONV_BLOCKS + ZERO_BLOCKS;

__global__ void prep_kernel(const float* __restrict__ x,
                            const float* __restrict__ fc,
                            float4* __restrict__ out4) {
    int blk = blockIdx.x;
    if (blk < FEAT_BLOCKS) {
        uint4* F4 = reinterpret_cast<uint4*>(F_scratch);
        int base = blk * 512 + threadIdx.x;      // element id = b*1024 + i
        float xv0 = x[base];
        float xv1 = x[base + 256];

        float s0, c0, s1, c1;
        __sincosf(xv0, &s0, &c0);
        __sincosf(xv1, &s1, &c1);

        union { __half h[8]; uint4 v; } uc0, us0, uc1, us1;
        float ck0 = c0, sk0 = s0, ck1 = c1, sk1 = s1;
        uc0.h[0] = __float2half_rn(c0);  us0.h[0] = __float2half_rn(s0);
        uc1.h[0] = __float2half_rn(c1);  us1.h[0] = __float2half_rn(s1);
#pragma unroll
        for (int k = 1; k < GRID; k++) {
            float cn0 = ck0 * c0 - sk0 * s0;
            float sn0 = sk0 * c0 + ck0 * s0;
            float cn1 = ck1 * c1 - sk1 * s1;
            float sn1 = sk1 * c1 + ck1 * s1;
            ck0 = cn0; sk0 = sn0; ck1 = cn1; sk1 = sn1;
            uc0.h[k] = __float2half_rn(ck0);  us0.h[k] = __float2half_rn(sk0);
            uc1.h[k] = __float2half_rn(ck1);  us1.h[k] = __float2half_rn(sk1);
        }
        int b0 = base >> 10,         i0 = base & 1023;
        int b1 = (base + 256) >> 10, i1 = (base + 256) & 1023;
        F4[(size_t)b0 * 2048 + i0]        = uc0.v;
        F4[(size_t)b0 * 2048 + 1024 + i0] = us0.v;
        F4[(size_t)b1 * 2048 + i1]        = uc1.v;
        F4[(size_t)b1 * 2048 + 1024 + i1] = us1.v;
    } else if (blk < FEAT_BLOCKS + WCONV_BLOCKS) {
        uint4* W4 = reinterpret_cast<uint4*>(W_scratch);
        int gid = (blk - FEAT_BLOCKS) * blockDim.x + threadIdx.x; // (t*1024+j)*1024+i
        int i = gid & 1023;
        int j = (gid >> 10) & 1023;
        int t = gid >> 20;

        const float4* src = reinterpret_cast<const float4*>(fc + (size_t)gid * 8);
        float4 a = src[0], b = src[1];

        union { __half h[8]; uint4 v; } u;
        u.h[0] = __float2half_rn(a.x); u.h[1] = __float2half_rn(a.y);
        u.h[2] = __float2half_rn(a.z); u.h[3] = __float2half_rn(a.w);
        u.h[4] = __float2half_rn(b.x); u.h[5] = __float2half_rn(b.y);
        u.h[6] = __float2half_rn(b.z); u.h[7] = __float2half_rn(b.w);

        W4[(size_t)j * 2048 + t * 1024 + i] = u.v;
    } else {
        int gid = (blk - FEAT_BLOCKS - WCONV_BLOCKS) * blockDim.x + threadIdx.x;
        out4[gid] = make_float4(0.f, 0.f, 0.f, 0.f);
    }
}

// ----------------------------------------------------------------------------
// Pass 2: mma.sync GEMM.  CTA 128x128xKT=64, 8 warps (2x4), warp 64x32.
// Split-K = 4: each CTA handles 64 of 256 K-iterations, REDG.v2 epilogue.
// ----------------------------------------------------------------------------
static constexpr int MT = 128;
static constexpr int NT = 128;
static constexpr int KT = 64;                 // 64 halves = 128 B per row
static constexpr int STAGES = 3;
static constexpr int SPLITK = 4;
static constexpr int ITERS_PER_CTA = KTOT / KT / SPLITK;   // 64

static constexpr int TILE_BYTES = MT * 128;              // 16384 per operand
static constexpr int STAGE_BYTES = 2 * TILE_BYTES;       // A + B = 32768
static constexpr int SMEM_BYTES = STAGES * STAGE_BYTES;  // 98304 per CTA

DI uint32_t swz(uint32_t off) { return off ^ ((off >> 3) & 0x70); }

DI void cp_async16(uint32_t dst, const void* src) {
    asm volatile("cp.async.cg.shared.global [%0], [%1], 16;"
                 :: "r"(dst), "l"(src) : "memory");
}
DI void cp_commit() { asm volatile("cp.async.commit_group;" ::: "memory"); }

DI void ldmatrix_x4(uint32_t* r, uint32_t addr) {
    asm volatile("ldmatrix.sync.aligned.m8n8.x4.shared.b16 {%0,%1,%2,%3}, [%4];"
                 : "=r"(r[0]), "=r"(r[1]), "=r"(r[2]), "=r"(r[3]) : "r"(addr));
}

DI void mma16816(float* c, const uint32_t* a, const uint32_t* b) {
    asm volatile(
        "mma.sync.aligned.m16n8k16.row.col.f32.f16.f16.f32 "
        "{%0,%1,%2,%3}, {%4,%5,%6,%7}, {%8,%9}, {%0,%1,%2,%3};"
        : "+f"(c[0]), "+f"(c[1]), "+f"(c[2]), "+f"(c[3])
        : "r"(a[0]), "r"(a[1]), "r"(a[2]), "r"(a[3]), "r"(b[0]), "r"(b[1]));
}

DI void red_add_v2(float* addr, float v0, float v1) {
    asm volatile("red.global.add.v2.f32 [%0], {%1, %2};"
                 :: "l"(addr), "f"(v0), "f"(v1) : "memory");
}

extern __shared__ char gemm_smem[];

DI void load_stage(int stage, int tid, uint32_t smem_u32,
                   int m0, int n0, int kiter_base) {
    int slot = stage % STAGES;
    uint32_t a_base = smem_u32 + slot * STAGE_BYTES;
    uint32_t b_base = a_base + TILE_BYTES;
    size_t koff = (size_t)(kiter_base + stage) * KT;
    const __half* Fp = F_scratch + (size_t)m0 * KTOT + koff;
    const __half* Wp = W_scratch + (size_t)n0 * KTOT + koff;

    // 128 rows x 8 chunks of 16B per operand; 256 threads -> 4 chunks each.
#pragma unroll
    for (int it = 0; it < 4; it++) {
        int c = tid + it * 256;
        int row = c >> 3, col = c & 7;
        cp_async16(a_base + swz((uint32_t)row * 128 + (uint32_t)col * 16),
                   Fp + (size_t)row * KTOT + col * 8);
    }
#pragma unroll
    for (int it = 0; it < 4; it++) {
        int c = tid + it * 256;
        int row = c >> 3, col = c & 7;
        cp_async16(b_base + swz((uint32_t)row * 128 + (uint32_t)col * 16),
                   Wp + (size_t)row * KTOT + col * 8);
    }
    cp_commit();
}

__global__ void __launch_bounds__(256, 2)
gemm_kernel(float* __restrict__ out) {
    uint32_t smem_u32 = (uint32_t)__cvta_generic_to_shared(gemm_smem);
    int tid = threadIdx.x;
    int wid = tid >> 5, lid = tid & 31;
    int wm = wid >> 2;          // 0..1 : warp M tile of 64
    int wn = wid & 3;           // 0..3 : warp N tile of 32
    int n0 = blockIdx.x * NT;
    int m0 = blockIdx.y * MT;
    int kiter_base = blockIdx.z * ITERS_PER_CTA;

    float acc[4][4][4];
#pragma unroll
    for (int mi = 0; mi < 4; mi++)
#pragma unroll
        for (int ni = 0; ni < 4; ni++)
#pragma unroll
            for (int q = 0; q < 4; q++) acc[mi][ni][q] = 0.0f;

    // ldmatrix lane address components (pre-swizzle, within tile)
    int a_row_lane = lid & 15;
    int a_koff_lane = (lid >> 4) << 4;               // 0 or 16 bytes
    int b_row_lane = (lid & 7) + ((lid >> 4) << 3);
    int b_koff_lane = ((lid >> 3) & 1) << 4;

    uint32_t a_lane_off = (uint32_t)(wm * 64 + a_row_lane) * 128 + a_koff_lane;
    uint32_t b_lane_off = (uint32_t)(wn * 32 + b_row_lane) * 128 + b_koff_lane;

    // Prologue: fill 2 of 3 stages.
    load_stage(0, tid, smem_u32, m0, n0, kiter_base);
    load_stage(1, tid, smem_u32, m0, n0, kiter_base);

    for (int s = 0; s < ITERS_PER_CTA; s++) {
        int slot = s % STAGES;

        if (s + 1 < ITERS_PER_CTA)
            asm volatile("cp.async.wait_group 1;" ::: "memory");
        else
            asm volatile("cp.async.wait_group 0;" ::: "memory");
        __syncthreads();   // all threads' stage-s data visible; slot of s-1 free

        if (s + 2 < ITERS_PER_CTA)
            load_stage(s + 2, tid, smem_u32, m0, n0, kiter_base);

        uint32_t a_base = smem_u32 + slot * STAGE_BYTES;
        uint32_t b_base = a_base + TILE_BYTES;

        // Per-warp phase stagger over the 4 k-sub-steps.
#pragma unroll
        for (int ks = 0; ks < 4; ks++) {
            uint32_t kb = (uint32_t)(((ks + wid) & 3) * 32);
            uint32_t af[4][4];
            uint32_t bf[4][2];
#pragma unroll
            for (int mi = 0; mi < 4; mi++)
                ldmatrix_x4(af[mi], a_base +
                            swz(a_lane_off + (uint32_t)(mi * 16) * 128 + kb));
#pragma unroll
            for (int g = 0; g < 2; g++) {
                uint32_t r[4];
                ldmatrix_x4(r, b_base +
                            swz(b_lane_off + (uint32_t)(g * 16) * 128 + kb));
                bf[g * 2 + 0][0] = r[0]; bf[g * 2 + 0][1] = r[1];
                bf[g * 2 + 1][0] = r[2]; bf[g * 2 + 1][1] = r[3];
            }
#pragma unroll
            for (int mi = 0; mi < 4; mi++)
#pragma unroll
                for (int ni = 0; ni < 4; ni++)
                    mma16816(acc[mi][ni], af[mi], bf[ni]);
        }
    }

    // Epilogue: accumulate partial tile into gmem via vector L2 reductions.
    int qr = lid >> 2;
    int qc = lid & 3;
#pragma unroll
    for (int mi = 0; mi < 4; mi++) {
        int row_a = m0 + wm * 64 + mi * 16 + qr;
        int row_b = row_a + 8;
#pragma unroll
        for (int ni = 0; ni < 4; ni++) {
            int col = n0 + wn * 32 + ni * 8 + qc * 2;
            red_add_v2(out + (size_t)row_a * OUTDIM + col,
                       acc[mi][ni][0], acc[mi][ni][1]);
            red_add_v2(out + (size_t)row_b * OUTDIM + col,
                       acc[mi][ni][2], acc[mi][ni][3]);
        }
    }
}

// ----------------------------------------------------------------------------
// kernel_launch
// ----------------------------------------------------------------------------
extern "C" void kernel_launch(void* const* d_in, const int* in_sizes, int n_in,
                              void* d_out, int out_size) {
    const float* x  = (const float*)d_in[0];    // [8192, 1024]
    const float* fc = (const float*)d_in[1];    // [2, 1024, 1024, 8]
    float* out = (float*)d_out;                 // [8192, 1024]

    prep_kernel<<<PREP_BLOCKS, 256>>>(x, fc, (float4*)out);

    cudaFuncSetAttribute(gemm_kernel,
                         cudaFuncAttributeMaxDynamicSharedMemorySize, SMEM_BYTES);
    gemm_kernel<<<dim3(OUTDIM / NT, BATCH / MT, SPLITK), 256, SMEM_BYTES>>>(out);
}

// round 15
// speedup vs baseline: 1.0720x; 1.0333x over previous
#include <cuda_runtime.h>
#include <cuda_fp16.h>
#include <cstdint>
#include <cstddef>

// ============================================================================
// NaiveFourierKANLayer on GB300 (sm_103a harness targets compute_103 ->
// tcgen05 unavailable; mma.sync HMMA path).
// GEMM: Y[8192,1024] = F[8192,16384] @ Wh[1024,16384]^T  (fp16 in, fp32 acc)
//   kidx = t*8192 + i*8 + k   (t=0 cos, t=1 sin; harmonic k+1)
// R15: R14 core; ONLY change is load_stage(s+2) moved to after the first
//      peeled ks sub-step (identical inline LDSM/MMA code), so the produce
//      burst issues under the first MMA block instead of pre-empting it.
//      Core: 128x128 CTA, 64x32 warps, 2 CTAs/SM, 3-stage cp.async,
//      split-K=4, ks stagger, red.v2 epilogue, contiguous-store prep.
// ============================================================================

#define DI __device__ __forceinline__

static constexpr int BATCH  = 8192;
static constexpr int INDIM  = 1024;
static constexpr int OUTDIM = 1024;
static constexpr int GRID   = 8;
static constexpr int KTOT   = INDIM * 2 * GRID;   // 16384

__device__ __half F_scratch[(size_t)BATCH * KTOT];    // 268 MB
__device__ __half W_scratch[(size_t)OUTDIM * KTOT];   // 32 MB

// ----------------------------------------------------------------------------
// Pass 1 (merged): features (2 elems/thread), W convert, output zero-fill.
// ----------------------------------------------------------------------------
static constexpr int FEAT_BLOCKS  = (BATCH * INDIM) / 512;          // 16384
static constexpr int WCONV_BLOCKS = (2 * OUTDIM * INDIM) / 256;     // 8192
static constexpr int ZERO_BLOCKS  = (BATCH * OUTDIM / 4) / 256;     // 8192
static constexpr int PREP_BLOCKS  = FEAT_BLOCKS + WCONV_BLOCKS + ZERO_BLOCKS;

__global__ void prep_kernel(const float* __restrict__ x,
                            const float* __restrict__ fc,
                            float4* __restrict__ out4) {
    int blk = blockIdx.x;
    if (blk < FEAT_BLOCKS) {
        uint4* F4 = reinterpret_cast<uint4*>(F_scratch);
        int base = blk * 512 + threadIdx.x;      // element id = b*1024 + i
        float xv0 = x[base];
        float xv1 = x[base + 256];

        float s0, c0, s1, c1;
        __sincosf(xv0, &s0, &c0);
        __sincosf(xv1, &s1, &c1);

        union { __half h[8]; uint4 v; } uc0, us0, uc1, us1;
        float ck0 = c0, sk0 = s0, ck1 = c1, sk1 = s1;
        uc0.h[0] = __float2half_rn(c0);  us0.h[0] = __float2half_rn(s0);
        uc1.h[0] = __float2half_rn(c1);  us1.h[0] = __float2half_rn(s1);
#pragma unroll
        for (int k = 1; k < GRID; k++) {
            float cn0 = ck0 * c0 - sk0 * s0;
            float sn0 = sk0 * c0 + ck0 * s0;
            float cn1 = ck1 * c1 - sk1 * s1;
            float sn1 = sk1 * c1 + ck1 * s1;
            ck0 = cn0; sk0 = sn0; ck1 = cn1; sk1 = sn1;
            uc0.h[k] = __float2half_rn(ck0);  us0.h[k] = __float2half_rn(sk0);
            uc1.h[k] = __float2half_rn(ck1);  us1.h[k] = __float2half_rn(sk1);
        }
        int b0 = base >> 10,         i0 = base & 1023;
        int b1 = (base + 256) >> 10, i1 = (base + 256) & 1023;
        F4[(size_t)b0 * 2048 + i0]        = uc0.v;
        F4[(size_t)b0 * 2048 + 1024 + i0] = us0.v;
        F4[(size_t)b1 * 2048 + i1]        = uc1.v;
        F4[(size_t)b1 * 2048 + 1024 + i1] = us1.v;
    } else if (blk < FEAT_BLOCKS + WCONV_BLOCKS) {
        uint4* W4 = reinterpret_cast<uint4*>(W_scratch);
        int gid = (blk - FEAT_BLOCKS) * blockDim.x + threadIdx.x; // (t*1024+j)*1024+i
        int i = gid & 1023;
        int j = (gid >> 10) & 1023;
        int t = gid >> 20;

        const float4* src = reinterpret_cast<const float4*>(fc + (size_t)gid * 8);
        float4 a = src[0], b = src[1];

        union { __half h[8]; uint4 v; } u;
        u.h[0] = __float2half_rn(a.x); u.h[1] = __float2half_rn(a.y);
        u.h[2] = __float2half_rn(a.z); u.h[3] = __float2half_rn(a.w);
        u.h[4] = __float2half_rn(b.x); u.h[5] = __float2half_rn(b.y);
        u.h[6] = __float2half_rn(b.z); u.h[7] = __float2half_rn(b.w);

        W4[(size_t)j * 2048 + t * 1024 + i] = u.v;
    } else {
        int gid = (blk - FEAT_BLOCKS - WCONV_BLOCKS) * blockDim.x + threadIdx.x;
        out4[gid] = make_float4(0.f, 0.f, 0.f, 0.f);
    }
}

// ----------------------------------------------------------------------------
// Pass 2: mma.sync GEMM.  CTA 128x128xKT=64, 8 warps (2x4), warp 64x32.
// Split-K = 4: each CTA handles 64 of 256 K-iterations, REDG.v2 epilogue.
// ----------------------------------------------------------------------------
static constexpr int MT = 128;
static constexpr int NT = 128;
static constexpr int KT = 64;                 // 64 halves = 128 B per row
static constexpr int STAGES = 3;
static constexpr int SPLITK = 4;
static constexpr int ITERS_PER_CTA = KTOT / KT / SPLITK;   // 64

static constexpr int TILE_BYTES = MT * 128;              // 16384 per operand
static constexpr int STAGE_BYTES = 2 * TILE_BYTES;       // A + B = 32768
static constexpr int SMEM_BYTES = STAGES * STAGE_BYTES;  // 98304 per CTA

DI uint32_t swz(uint32_t off) { return off ^ ((off >> 3) & 0x70); }

DI void cp_async16(uint32_t dst, const void* src) {
    asm volatile("cp.async.cg.shared.global [%0], [%1], 16;"
                 :: "r"(dst), "l"(src) : "memory");
}
DI void cp_commit() { asm volatile("cp.async.commit_group;" ::: "memory"); }

DI void ldmatrix_x4(uint32_t* r, uint32_t addr) {
    asm volatile("ldmatrix.sync.aligned.m8n8.x4.shared.b16 {%0,%1,%2,%3}, [%4];"
                 : "=r"(r[0]), "=r"(r[1]), "=r"(r[2]), "=r"(r[3]) : "r"(addr));
}

DI void mma16816(float* c, const uint32_t* a, const uint32_t* b) {
    asm volatile(
        "mma.sync.aligned.m16n8k16.row.col.f32.f16.f16.f32 "
        "{%0,%1,%2,%3}, {%4,%5,%6,%7}, {%8,%9}, {%0,%1,%2,%3};"
        : "+f"(c[0]), "+f"(c[1]), "+f"(c[2]), "+f"(c[3])
        : "r"(a[0]), "r"(a[1]), "r"(a[2]), "r"(a[3]), "r"(b[0]), "r"(b[1]));
}

DI void red_add_v2(float* addr, float v0, float v1) {
    asm volatile("red.global.add.v2.f32 [%0], {%1, %2};"
                 :: "l"(addr), "f"(v0), "f"(v1) : "memory");
}

extern __shared__ char gemm_smem[];

DI void load_stage(int stage, int tid, uint32_t smem_u32,
                   int m0, int n0, int kiter_base) {
    int slot = stage % STAGES;
    uint32_t a_base = smem_u32 + slot * STAGE_BYTES;
    uint32_t b_base = a_base + TILE_BYTES;
    size_t koff = (size_t)(kiter_base + stage) * KT;
    const __half* Fp = F_scratch + (size_t)m0 * KTOT + koff;
    const __half* Wp = W_scratch + (size_t)n0 * KTOT + koff;

#pragma unroll
    for (int it = 0; it < 4; it++) {
        int c = tid + it * 256;
        int row = c >> 3, col = c & 7;
        cp_async16(a_base + swz((uint32_t)row * 128 + (uint32_t)col * 16),
                   Fp + (size_t)row * KTOT + col * 8);
    }
#pragma unroll
    for (int it = 0; it < 4; it++) {
        int c = tid + it * 256;
        int row = c >> 3, col = c & 7;
        cp_async16(b_base + swz((uint32_t)row * 128 + (uint32_t)col * 16),
                   Wp + (size_t)row * KTOT + col * 8);
    }
    cp_commit();
}

__global__ void __launch_bounds__(256, 2)
gemm_kernel(float* __restrict__ out) {
    uint32_t smem_u32 = (uint32_t)__cvta_generic_to_shared(gemm_smem);
    int tid = threadIdx.x;
    int wid = tid >> 5, lid = tid & 31;
    int wm = wid >> 2;          // 0..1 : warp M tile of 64
    int wn = wid & 3;           // 0..3 : warp N tile of 32
    int n0 = blockIdx.x * NT;
    int m0 = blockIdx.y * MT;
    int kiter_base = blockIdx.z * ITERS_PER_CTA;

    float acc[4][4][4];
#pragma unroll
    for (int mi = 0; mi < 4; mi++)
#pragma unroll
        for (int ni = 0; ni < 4; ni++)
#pragma unroll
            for (int q = 0; q < 4; q++) acc[mi][ni][q] = 0.0f;

    // ldmatrix lane address components (pre-swizzle, within tile)
    int a_row_lane = lid & 15;
    int a_koff_lane = (lid >> 4) << 4;               // 0 or 16 bytes
    int b_row_lane = (lid & 7) + ((lid >> 4) << 3);
    int b_koff_lane = ((lid >> 3) & 1) << 4;

    uint32_t a_lane_off = (uint32_t)(wm * 64 + a_row_lane) * 128 + a_koff_lane;
    uint32_t b_lane_off = (uint32_t)(wn * 32 + b_row_lane) * 128 + b_koff_lane;

    // Prologue: fill 2 of 3 stages.
    load_stage(0, tid, smem_u32, m0, n0, kiter_base);
    load_stage(1, tid, smem_u32, m0, n0, kiter_base);

    for (int s = 0; s < ITERS_PER_CTA; s++) {
        int slot = s % STAGES;

        if (s + 1 < ITERS_PER_CTA)
            asm volatile("cp.async.wait_group 1;" ::: "memory");
        else
            asm volatile("cp.async.wait_group 0;" ::: "memory");
        __syncthreads();   // all threads' stage-s data visible; slot of s-1 free

        uint32_t a_base = smem_u32 + slot * STAGE_BYTES;
        uint32_t b_base = a_base + TILE_BYTES;

        // ---- peeled ks = 0 (identical inline code to loop body) ----
        {
            uint32_t kb = (uint32_t)(((0 + wid) & 3) * 32);
            uint32_t af[4][4];
            uint32_t bf[4][2];
#pragma unroll
            for (int mi = 0; mi < 4; mi++)
                ldmatrix_x4(af[mi], a_base +
                            swz(a_lane_off + (uint32_t)(mi * 16) * 128 + kb));
#pragma unroll
            for (int g = 0; g < 2; g++) {
                uint32_t r[4];
                ldmatrix_x4(r, b_base +
                            swz(b_lane_off + (uint32_t)(g * 16) * 128 + kb));
                bf[g * 2 + 0][0] = r[0]; bf[g * 2 + 0][1] = r[1];
                bf[g * 2 + 1][0] = r[2]; bf[g * 2 + 1][1] = r[3];
            }
#pragma unroll
            for (int mi = 0; mi < 4; mi++)
#pragma unroll
                for (int ni = 0; ni < 4; ni++)
                    mma16816(acc[mi][ni], af[mi], bf[ni]);
        }

        // Produce burst issues while ks=0 MMAs drain.
        if (s + 2 < ITERS_PER_CTA)
            load_stage(s + 2, tid, smem_u32, m0, n0, kiter_base);

        // ---- ks = 1..3 (per-warp phase stagger) ----
#pragma unroll
        for (int ks = 1; ks < 4; ks++) {
            uint32_t kb = (uint32_t)(((ks + wid) & 3) * 32);
            uint32_t af[4][4];
            uint32_t bf[4][2];
#pragma unroll
            for (int mi = 0; mi < 4; mi++)
                ldmatrix_x4(af[mi], a_base +
                            swz(a_lane_off + (uint32_t)(mi * 16) * 128 + kb));
#pragma unroll
            for (int g = 0; g < 2; g++) {
                uint32_t r[4];
                ldmatrix_x4(r, b_base +
                            swz(b_lane_off + (uint32_t)(g * 16) * 128 + kb));
                bf[g * 2 + 0][0] = r[0]; bf[g * 2 + 0][1] = r[1];
                bf[g * 2 + 1][0] = r[2]; bf[g * 2 + 1][1] = r[3];
            }
#pragma unroll
            for (int mi = 0; mi < 4; mi++)
#pragma unroll
                for (int ni = 0; ni < 4; ni++)
                    mma16816(acc[mi][ni], af[mi], bf[ni]);
        }
    }

    // Epilogue: accumulate partial tile into gmem via vector L2 reductions.
    int qr = lid >> 2;
    int qc = lid & 3;
#pragma unroll
    for (int mi = 0; mi < 4; mi++) {
        int row_a = m0 + wm * 64 + mi * 16 + qr;
        int row_b = row_a + 8;
#pragma unroll
        for (int ni = 0; ni < 4; ni++) {
            int col = n0 + wn * 32 + ni * 8 + qc * 2;
            red_add_v2(out + (size_t)row_a * OUTDIM + col,
                       acc[mi][ni][0], acc[mi][ni][1]);
            red_add_v2(out + (size_t)row_b * OUTDIM + col,
                       acc[mi][ni][2], acc[mi][ni][3]);
        }
    }
}

// ----------------------------------------------------------------------------
// kernel_launch
// ----------------------------------------------------------------------------
extern "C" void kernel_launch(void* const* d_in, const int* in_sizes, int n_in,
                              void* d_out, int out_size) {
    const float* x  = (const float*)d_in[0];    // [8192, 1024]
    const float* fc = (const float*)d_in[1];    // [2, 1024, 1024, 8]
    float* out = (float*)d_out;                 // [8192, 1024]

    prep_kernel<<<PREP_BLOCKS, 256>>>(x, fc, (float4*)out);

    cudaFuncSetAttribute(gemm_kernel,
                         cudaFuncAttributeMaxDynamicSharedMemorySize, SMEM_BYTES);
    gemm_kernel<<<dim3(OUTDIM / NT, BATCH / MT, SPLITK), 256, SMEM_BYTES>>>(out);
}